// round 15
// baseline (speedup 1.0000x reference)
#include <cuda_runtime.h>
#include <cuda_bf16.h>
#include <cuda_fp16.h>
#include <cstdint>

#define H_HEADS 16
#define DHEAD   64
#define RMS_EPS 1.1920928955078125e-07f
#define MAXTOK  4096
#define LOG2E   1.4426950408889634f
#define FIXMAX  12.0f

// ---------------- scratch ----------------
__device__ __half g_a16 [MAXTOK * 1024];
__device__ __half g_b16 [1024 * 1024];
__device__ __half g_c16 [1024 * 1024];
__device__ __half g_q16 [MAXTOK * 1024];
__device__ __half g_kv16[MAXTOK * 1024];

// ---------------- helpers ----------------
__device__ __forceinline__ uint32_t smem_u32(const void* p) {
    uint32_t a;
    asm("{ .reg .u64 t; cvta.to.shared.u64 t, %1; cvt.u32.u64 %0, t; }" : "=r"(a) : "l"(p));
    return a;
}

#define LDSM_X4(r0, r1, r2, r3, addr) \
    asm volatile("ldmatrix.sync.aligned.m8n8.x4.shared.b16 {%0,%1,%2,%3}, [%4];" \
                 : "=r"(r0), "=r"(r1), "=r"(r2), "=r"(r3) : "r"(addr))

#define LDSM_X4_T(r0, r1, r2, r3, addr) \
    asm volatile("ldmatrix.sync.aligned.m8n8.x4.trans.shared.b16 {%0,%1,%2,%3}, [%4];" \
                 : "=r"(r0), "=r"(r1), "=r"(r2), "=r"(r3) : "r"(addr))

#define MMA_FP16(c0, c1, c2, c3, a0, a1, a2, a3, b0, b1) \
    asm volatile("mma.sync.aligned.m16n8k16.row.col.f32.f16.f16.f32 " \
                 "{%0,%1,%2,%3}, {%4,%5,%6,%7}, {%8,%9}, {%0,%1,%2,%3};" \
                 : "+f"(c0), "+f"(c1), "+f"(c2), "+f"(c3) \
                 : "r"(a0), "r"(a1), "r"(a2), "r"(a3), "r"(b0), "r"(b1))

#define CP16(saddr, gptr) \
    asm volatile("cp.async.cg.shared.global [%0], [%1], 16;" :: "r"(saddr), "l"(gptr))
#define CPA16(saddr, gptr) \
    asm volatile("cp.async.ca.shared.global [%0], [%1], 16;" :: "r"(saddr), "l"(gptr))
#define CP_COMMIT() asm volatile("cp.async.commit_group;" ::: "memory")
#define CP_WAIT1()  asm volatile("cp.async.wait_group 1;" ::: "memory")
#define CP_WAIT0()  asm volatile("cp.async.wait_group 0;" ::: "memory")

__device__ __forceinline__ uint32_t pack_h2(float a, float b) {
    __half2 t(__float2half(a), __float2half(b));
    return *(uint32_t*)&t;
}

// ---------------------------------------------------------------------------
// prep_all: blocks [0, qblocks) do q prep; remaining blocks convert weights.
// ---------------------------------------------------------------------------
__global__ __launch_bounds__(256) void prep_all(
    const float* __restrict__ x, const float* __restrict__ cosb,
    const float* __restrict__ sinb,
    const float* __restrict__ kv_w, const float* __restrict__ proj_w,
    __half* __restrict__ a16, __half* __restrict__ q16,
    __half* __restrict__ b16, __half* __restrict__ c16,
    float qscale, int T, int total_heads, int qblocks, int wn4)
{
    if ((int)blockIdx.x >= qblocks) {
        int idx = (blockIdx.x - qblocks) * 256 + threadIdx.x;
        const float* src; __half* dst;
        if (idx < wn4) { src = kv_w; dst = b16; }
        else           { src = proj_w; dst = c16; idx -= wn4; }
        if (idx < wn4) {
            float4 v = ((const float4*)src)[idx];
            ((uint32_t*)dst)[2 * idx]     = pack_h2(v.x, v.y);
            ((uint32_t*)dst)[2 * idx + 1] = pack_h2(v.z, v.w);
        }
        return;
    }

    int w = blockIdx.x * 8 + (threadIdx.x >> 5);
    if (w >= total_heads) return;
    int lane = threadIdx.x & 31;
    int h = w % H_HEADS;
    int t = (w / H_HEADS) % T;
    int b = w / (H_HEADS * T);

    size_t ibase = (size_t)w * DHEAD;
    float x1 = x[ibase + lane];
    float x2 = x[ibase + 32 + lane];

    a16[ibase + lane]      = __float2half(x1);
    a16[ibase + 32 + lane] = __float2half(x2);

    float c  = cosb[t * 32 + lane];
    float s  = sinb[t * 32 + lane];
    float o1 = x1 * c + x2 * s;
    float o2 = -x1 * s + x2 * c;

    float ss = o1 * o1 + o2 * o2;
#pragma unroll
    for (int off = 16; off; off >>= 1)
        ss += __shfl_xor_sync(0xffffffffu, ss, off);
    float r = rsqrtf(ss * (1.0f / 64.0f) + RMS_EPS) * qscale;

    size_t obase = ((size_t)(b * H_HEADS + h) * T + t) * DHEAD;
    q16[obase + lane]      = __float2half(o1 * r);
    q16[obase + 32 + lane] = __float2half(o2 * r);
}

// ---------------------------------------------------------------------------
// 2-stage cp.async fp16 NT GEMM (R13 config — measured at HMMA floor).
// ---------------------------------------------------------------------------
#define KCH2   32
#define ROWB2  80
#define MATB2  (128 * ROWB2)
#define STB2   (2 * MATB2)       // 20480 per stage
#define GEMM_SMEM (2 * STB2)     // 40960

template <bool FUSE_ROPE>
__global__ __launch_bounds__(256, 2) void gemm_mma(
    const __half* __restrict__ A, const __half* __restrict__ B,
    float* __restrict__ C,
    const float* __restrict__ cosb, const float* __restrict__ sinb,
    __half* __restrict__ O16,
    int M, int N, int K, int T)
{
    extern __shared__ char smem[];
    const uint32_t sb = smem_u32(smem);

    const int tid  = threadIdx.x;
    const int wid  = tid >> 5;
    const int lane = tid & 31;
    const int m0 = blockIdx.y * 128, n0 = blockIdx.x * 128;

    const int wm = (wid & 3) * 32;
    const int wn = (wid >> 2) * 64;

    const int a_row = (lane & 7) + (lane & 8);
    const int a_col = (lane >> 4) * 16;
    const int b_row = (lane & 7) + ((lane >> 4) & 1) * 8;
    const int b_col = ((lane >> 3) & 1) * 16;

    const int grow = tid >> 1;
    const uint32_t s_off = (uint32_t)grow * ROWB2 + (tid & 1) * 32;
    const int gelem = (tid & 1) * 16;

    const __half* gA = A + (size_t)(m0 + grow) * K + gelem;
    const __half* gB = B + (size_t)(n0 + grow) * K + gelem;

    float c[2][8][4];
#pragma unroll
    for (int i = 0; i < 2; i++)
#pragma unroll
        for (int j = 0; j < 8; j++)
#pragma unroll
            for (int e = 0; e < 4; e++) c[i][j][e] = 0.f;

    const int nchunk = K / KCH2;

    auto fill = [&](int stage, int ch) {
        const int k0 = ch * KCH2;
        uint32_t s0 = sb + stage * STB2 + s_off;
        const __half* a0 = gA + k0;
        const __half* b0 = gB + k0;
        CP16(s0,         a0);  CP16(s0 + 16,         a0 + 8);
        CP16(s0 + MATB2, b0);  CP16(s0 + MATB2 + 16, b0 + 8);
    };

    fill(0, 0);
    CP_COMMIT();

    for (int ch = 0; ch < nchunk; ch++) {
        const int st = ch & 1;
        if (ch + 1 < nchunk) { fill(st ^ 1, ch + 1); CP_COMMIT(); CP_WAIT1(); }
        else                 { CP_WAIT0(); }
        __syncthreads();

        const uint32_t sA = sb + st * STB2;
        const uint32_t sB = sA + MATB2;

#pragma unroll
        for (int ks = 0; ks < 2; ks++) {
            const int kb = ks * 32;
            uint32_t ah[2][4], bh[4][4];
#pragma unroll
            for (int mi = 0; mi < 2; mi++) {
                uint32_t addr = sA + (uint32_t)(wm + mi * 16 + a_row) * ROWB2 + kb + a_col;
                LDSM_X4(ah[mi][0], ah[mi][1], ah[mi][2], ah[mi][3], addr);
            }
#pragma unroll
            for (int nb = 0; nb < 4; nb++) {
                uint32_t addr = sB + (uint32_t)(wn + nb * 16 + b_row) * ROWB2 + kb + b_col;
                LDSM_X4(bh[nb][0], bh[nb][1], bh[nb][2], bh[nb][3], addr);
            }
#pragma unroll
            for (int mi = 0; mi < 2; mi++)
#pragma unroll
                for (int nb = 0; nb < 4; nb++)
#pragma unroll
                    for (int sj = 0; sj < 2; sj++) {
                        float* cc = c[mi][nb * 2 + sj];
                        MMA_FP16(cc[0], cc[1], cc[2], cc[3],
                                 ah[mi][0], ah[mi][1], ah[mi][2], ah[mi][3],
                                 bh[nb][sj * 2], bh[nb][sj * 2 + 1]);
                    }
        }
        __syncthreads();
    }

    const int g  = lane >> 2;
    const int t2 = (lane & 3) * 2;

    if (!FUSE_ROPE) {
#pragma unroll
        for (int mi = 0; mi < 2; mi++) {
            float* r0 = C + (size_t)(m0 + wm + mi * 16 + g) * N + n0 + wn + t2;
            float* r1 = r0 + 8 * N;
#pragma unroll
            for (int nj = 0; nj < 8; nj++) {
                *(float2*)(r0 + nj * 8) = make_float2(c[mi][nj][0], c[mi][nj][1]);
                *(float2*)(r1 + nj * 8) = make_float2(c[mi][nj][2], c[mi][nj][3]);
            }
        }
    } else {
        const int h = (n0 + wn) >> 6;
#pragma unroll
        for (int mi = 0; mi < 2; mi++) {
#pragma unroll
            for (int half = 0; half < 2; half++) {
                const int m = m0 + wm + mi * 16 + g + half * 8;
                const int b = m / T, t = m % T;
                float o1[4][2], o2[4][2];
                float ss = 0.f;
#pragma unroll
                for (int nj = 0; nj < 4; nj++) {
#pragma unroll
                    for (int e = 0; e < 2; e++) {
                        const int d = nj * 8 + t2 + e;
                        float x1 = c[mi][nj][half * 2 + e];
                        float x2 = c[mi][nj + 4][half * 2 + e];
                        float co = cosb[t * 32 + d];
                        float si = sinb[t * 32 + d];
                        float a = x1 * co + x2 * si;
                        float bb = -x1 * si + x2 * co;
                        o1[nj][e] = a; o2[nj][e] = bb;
                        ss += a * a + bb * bb;
                    }
                }
                ss += __shfl_xor_sync(0xffffffffu, ss, 1);
                ss += __shfl_xor_sync(0xffffffffu, ss, 2);
                float r = rsqrtf(ss * (1.0f / 64.0f) + RMS_EPS);
                const size_t ob = ((size_t)(b * H_HEADS + h) * T + t) * DHEAD + t2;
#pragma unroll
                for (int nj = 0; nj < 4; nj++) {
                    *(uint32_t*)(O16 + ob + nj * 8)      = pack_h2(o1[nj][0] * r, o1[nj][1] * r);
                    *(uint32_t*)(O16 + ob + 32 + nj * 8) = pack_h2(o2[nj][0] * r, o2[nj][1] * r);
                }
            }
        }
    }
}

// ---------------------------------------------------------------------------
// Sliding-window attention, fp16, 128-row q-tile (R14 config — confirmed win):
// 8 warps = 4 m-warps (x2 m-frags) x 2 key-groups; cp.async.ca KV pipeline.
// ---------------------------------------------------------------------------
#define ATT_ROWB 144
#define ATT_MAT  (64 * ATT_ROWB)

__global__ __launch_bounds__(256, 2) void attn_mma(
    const __half* __restrict__ Q16, const __half* __restrict__ KV16,
    __half* __restrict__ Out,
    const int* __restrict__ wl, int T)
{
    __shared__ char smc[2 * ATT_MAT];
    const uint32_t sbase = smem_u32(smc);

    const int tid = threadIdx.x, wid = tid >> 5, lane = tid & 31;
    const int mwarp = wid & 3, kgrp = wid >> 2;
    const int qt = blockIdx.x, h = blockIdx.y, b = blockIdx.z;
    const int q0 = qt * 128;
    const int W = *wl;
    const size_t hb = (size_t)(b * H_HEADS + h) * T * DHEAD;

    const int lrow = tid >> 2;
    const uint32_t s_off = (uint32_t)lrow * ATT_ROWB + (tid & 3) * 32;
    const int gcol = (tid & 3) * 16;

    const int a_row  = (lane & 7) + (lane & 8);
    const int a_colB = (lane >> 4) * 16;
    const int b_row  = (lane & 7) + ((lane >> 4) & 1) * 8;
    const int b_colB = ((lane >> 3) & 1) * 16;
    const int t_m = lane >> 3, t_r = lane & 7;

    auto fill_kv = [&](int st, int k0) {
        uint32_t s0 = sbase + st * ATT_MAT + s_off;
        const __half* gk = KV16 + hb + (size_t)(k0 + lrow) * DHEAD + gcol;
        CPA16(s0, gk);  CPA16(s0 + 16, gk + 8);
    };

    // stage Q: rows 0-63 in stage0, 64-127 in stage1; extract both m-frags
    {
        uint32_t s0 = sbase + s_off;
        const __half* gq = Q16 + hb + (size_t)(q0 + lrow) * DHEAD + gcol;
        CPA16(s0, gq);              CPA16(s0 + 16, gq + 8);
        const __half* gq1 = gq + (size_t)64 * DHEAD;
        CPA16(s0 + ATT_MAT, gq1);   CPA16(s0 + ATT_MAT + 16, gq1 + 8);
        CP_COMMIT();
        CP_WAIT0();
    }
    __syncthreads();
    uint32_t qf[2][4][4];
#pragma unroll
    for (int mi = 0; mi < 2; mi++)
#pragma unroll
        for (int kc = 0; kc < 4; kc++) {
            uint32_t ad = sbase + mi * ATT_MAT
                        + (uint32_t)(mwarp * 16 + a_row) * ATT_ROWB + kc * 32 + a_colB;
            LDSM_X4(qf[mi][kc][0], qf[mi][kc][1], qf[mi][kc][2], qf[mi][kc][3], ad);
        }
    __syncthreads();

    float o[2][8][4];
#pragma unroll
    for (int mi = 0; mi < 2; mi++)
#pragma unroll
        for (int i = 0; i < 8; i++)
#pragma unroll
            for (int e = 0; e < 4; e++) o[mi][i][e] = 0.f;
    float lsum[2][2] = {{0.f, 0.f}, {0.f, 0.f}};

    int lo_t = q0 - W; if (lo_t < 0) lo_t = 0;
    const int kt_lo = lo_t >> 6;
    const int kt_hi = (q0 + 127) >> 6;

    fill_kv(0, kt_lo * 64);
    CP_COMMIT();

    for (int kt = kt_lo; kt <= kt_hi; kt++) {
        const int k0 = kt * 64;
        const int st = (kt - kt_lo) & 1;
        if (kt < kt_hi) { fill_kv(st ^ 1, k0 + 64); CP_COMMIT(); CP_WAIT1(); }
        else            { CP_WAIT0(); }
        __syncthreads();

        const uint32_t sK = sbase + st * ATT_MAT;
        const bool fullt = (k0 + 63 <= q0) && (q0 + 127 - k0 <= W);

#pragma unroll
        for (int nc = 0; nc < 2; nc++) {
            const int n16 = kgrp * 2 + nc;

            float s[2][2][4];
#pragma unroll
            for (int mi = 0; mi < 2; mi++)
#pragma unroll
                for (int sj = 0; sj < 2; sj++)
#pragma unroll
                    for (int e = 0; e < 4; e++) s[mi][sj][e] = 0.f;

#pragma unroll
            for (int kc = 0; kc < 4; kc++) {
                uint32_t bf[4];
                uint32_t ad = sK + (uint32_t)(n16 * 16 + b_row) * ATT_ROWB + kc * 32 + b_colB;
                LDSM_X4(bf[0], bf[1], bf[2], bf[3], ad);
#pragma unroll
                for (int mi = 0; mi < 2; mi++) {
                    MMA_FP16(s[mi][0][0], s[mi][0][1], s[mi][0][2], s[mi][0][3],
                             qf[mi][kc][0], qf[mi][kc][1], qf[mi][kc][2], qf[mi][kc][3],
                             bf[0], bf[1]);
                    MMA_FP16(s[mi][1][0], s[mi][1][1], s[mi][1][2], s[mi][1][3],
                             qf[mi][kc][0], qf[mi][kc][1], qf[mi][kc][2], qf[mi][kc][3],
                             bf[2], bf[3]);
                }
            }

            if (!fullt) {
#pragma unroll
                for (int mi = 0; mi < 2; mi++) {
                    const int qr = q0 + mi * 64 + mwarp * 16 + (lane >> 2);
#pragma unroll
                    for (int sj = 0; sj < 2; sj++) {
                        const int kb = k0 + (n16 * 2 + sj) * 8 + (lane & 3) * 2;
#pragma unroll
                        for (int e = 0; e < 4; e++) {
                            int qq = qr + ((e >= 2) ? 8 : 0);
                            int kk = kb + (e & 1);
                            if (kk > qq || qq - kk > W) s[mi][sj][e] = -1e30f;
                        }
                    }
                }
            }

            uint32_t pf[2][4];
#pragma unroll
            for (int mi = 0; mi < 2; mi++) {
#pragma unroll
                for (int sj = 0; sj < 2; sj++)
#pragma unroll
                    for (int e = 0; e < 4; e++) {
                        float p = exp2f(s[mi][sj][e] - FIXMAX);
                        s[mi][sj][e] = p;
                        lsum[mi][e >> 1] += p;
                    }
                pf[mi][0] = pack_h2(s[mi][0][0], s[mi][0][1]);
                pf[mi][1] = pack_h2(s[mi][0][2], s[mi][0][3]);
                pf[mi][2] = pack_h2(s[mi][1][0], s[mi][1][1]);
                pf[mi][3] = pack_h2(s[mi][1][2], s[mi][1][3]);
            }

#pragma unroll
            for (int dg = 0; dg < 4; dg++) {
                uint32_t vf[4];
                uint32_t ad = sK + (uint32_t)(n16 * 16 + t_r + (t_m & 1) * 8) * ATT_ROWB
                            + dg * 32 + (t_m >> 1) * 16;
                LDSM_X4_T(vf[0], vf[1], vf[2], vf[3], ad);
#pragma unroll
                for (int mi = 0; mi < 2; mi++) {
                    float* c0 = o[mi][dg * 2];
                    float* c1 = o[mi][dg * 2 + 1];
                    MMA_FP16(c0[0], c0[1], c0[2], c0[3],
                             pf[mi][0], pf[mi][1], pf[mi][2], pf[mi][3], vf[0], vf[1]);
                    MMA_FP16(c1[0], c1[1], c1[2], c1[3],
                             pf[mi][0], pf[mi][1], pf[mi][2], pf[mi][3], vf[2], vf[3]);
                }
            }
        }
        __syncthreads();
    }

    // epilogue: two-pass cross-group reduce (linear partials add)
    float* red = (float*)smc;
    const int g = lane >> 2, t2 = (lane & 3) * 2;
#pragma unroll
    for (int mi = 0; mi < 2; mi++) {
        __syncthreads();
        if (kgrp == 1) {
            float* dst = red + (tid - 128) * 34;
#pragma unroll
            for (int i = 0; i < 8; i++)
#pragma unroll
                for (int e = 0; e < 4; e++) dst[i * 4 + e] = o[mi][i][e];
            dst[32] = lsum[mi][0];
            dst[33] = lsum[mi][1];
        }
        __syncthreads();
        if (kgrp == 0) {
            const float* src = red + tid * 34;
            float oo[8][4];
#pragma unroll
            for (int i = 0; i < 8; i++)
#pragma unroll
                for (int e = 0; e < 4; e++) oo[i][e] = o[mi][i][e] + src[i * 4 + e];
            float s0 = lsum[mi][0] + src[32];
            float s1 = lsum[mi][1] + src[33];
            s0 += __shfl_xor_sync(0xffffffffu, s0, 1);
            s0 += __shfl_xor_sync(0xffffffffu, s0, 2);
            s1 += __shfl_xor_sync(0xffffffffu, s1, 1);
            s1 += __shfl_xor_sync(0xffffffffu, s1, 2);
            const float inv0 = 1.f / s0;
            const float inv1 = 1.f / s1;
            const size_t r0 = (size_t)(b * T + q0 + mi * 64 + mwarp * 16 + g) * 1024 + h * 64 + t2;
            const size_t r1 = r0 + (size_t)8 * 1024;
#pragma unroll
            for (int nj = 0; nj < 8; nj++) {
                *(uint32_t*)(Out + r0 + nj * 8) = pack_h2(oo[nj][0] * inv0, oo[nj][1] * inv0);
                *(uint32_t*)(Out + r1 + nj * 8) = pack_h2(oo[nj][2] * inv1, oo[nj][3] * inv1);
            }
        }
    }
}

// ---------------------------------------------------------------------------
extern "C" void kernel_launch(void* const* d_in, const int* in_sizes, int n_in,
                              void* d_out, int out_size)
{
    const float* x      = (const float*)d_in[0];
    const float* cosb   = (const float*)d_in[1];
    const float* sinb   = (const float*)d_in[2];
    const float* kv_w   = (const float*)d_in[3];
    const float* proj_w = (const float*)d_in[4];
    const int* wl       = (n_in >= 6) ? (const int*)d_in[5] : nullptr;

    const int T = in_sizes[1] / 32;
    const int C = 1024;
    const int B = in_sizes[0] / (T * C);
    const int M = B * T;
    const int total_heads = M * H_HEADS;

    __half *a16, *b16, *c16, *q16, *kv16;
    cudaGetSymbolAddress((void**)&a16,  g_a16);
    cudaGetSymbolAddress((void**)&b16,  g_b16);
    cudaGetSymbolAddress((void**)&c16,  g_c16);
    cudaGetSymbolAddress((void**)&q16,  g_q16);
    cudaGetSymbolAddress((void**)&kv16, g_kv16);

    cudaFuncSetAttribute(gemm_mma<true>,  cudaFuncAttributeMaxDynamicSharedMemorySize, GEMM_SMEM);
    cudaFuncSetAttribute(gemm_mma<false>, cudaFuncAttributeMaxDynamicSharedMemorySize, GEMM_SMEM);

    // 1) fused prep: q rope/rms + x fp16 + both weight conversions
    {
        const int qblocks = (total_heads + 7) / 8;
        const int wn4 = C * C / 4;
        const int wblocks = (2 * wn4 + 255) / 256;
        prep_all<<<qblocks + wblocks, 256>>>(x, cosb, sinb, kv_w, proj_w,
                                             a16, q16, b16, c16,
                                             0.125f * LOG2E, T, total_heads,
                                             qblocks, wn4);
    }
    // 2) kv = rope(rms(x @ kv_w^T)), fused epilogue
    {
        dim3 grid(C / 128, M / 128);
        gemm_mma<true><<<grid, 256, GEMM_SMEM>>>(a16, b16, nullptr,
                                                 cosb, sinb, kv16, M, C, C, T);
    }
    // 3) attention
    {
        dim3 grid(T / 128, H_HEADS, B);
        attn_mma<<<grid, 256>>>(q16, kv16, a16, wl, T);
    }
    // 4) out = attn @ proj_w^T
    {
        dim3 grid(C / 128, M / 128);
        gemm_mma<false><<<grid, 256, GEMM_SMEM>>>(a16, c16, (float*)d_out,
                                                  nullptr, nullptr, nullptr, M, C, C, T);
    }
}

// round 16
// speedup vs baseline: 1.0352x; 1.0352x over previous
#include <cuda_runtime.h>
#include <cuda_bf16.h>
#include <cuda_fp16.h>
#include <cstdint>

#define H_HEADS 16
#define DHEAD   64
#define RMS_EPS 1.1920928955078125e-07f
#define MAXTOK  4096
#define LOG2E   1.4426950408889634f

// ---------------- scratch ----------------
__device__ __half g_a16 [MAXTOK * 1024];
__device__ __half g_b16 [1024 * 1024];
__device__ __half g_c16 [1024 * 1024];
__device__ __half g_q16 [MAXTOK * 1024];
__device__ __half g_kv16[MAXTOK * 1024];

// ---------------- helpers ----------------
__device__ __forceinline__ uint32_t smem_u32(const void* p) {
    uint32_t a;
    asm("{ .reg .u64 t; cvta.to.shared.u64 t, %1; cvt.u32.u64 %0, t; }" : "=r"(a) : "l"(p));
    return a;
}

#define LDSM_X4(r0, r1, r2, r3, addr) \
    asm volatile("ldmatrix.sync.aligned.m8n8.x4.shared.b16 {%0,%1,%2,%3}, [%4];" \
                 : "=r"(r0), "=r"(r1), "=r"(r2), "=r"(r3) : "r"(addr))

#define LDSM_X4_T(r0, r1, r2, r3, addr) \
    asm volatile("ldmatrix.sync.aligned.m8n8.x4.trans.shared.b16 {%0,%1,%2,%3}, [%4];" \
                 : "=r"(r0), "=r"(r1), "=r"(r2), "=r"(r3) : "r"(addr))

#define MMA_FP16(c0, c1, c2, c3, a0, a1, a2, a3, b0, b1) \
    asm volatile("mma.sync.aligned.m16n8k16.row.col.f32.f16.f16.f32 " \
                 "{%0,%1,%2,%3}, {%4,%5,%6,%7}, {%8,%9}, {%0,%1,%2,%3};" \
                 : "+f"(c0), "+f"(c1), "+f"(c2), "+f"(c3) \
                 : "r"(a0), "r"(a1), "r"(a2), "r"(a3), "r"(b0), "r"(b1))

#define CP16(saddr, gptr) \
    asm volatile("cp.async.cg.shared.global [%0], [%1], 16;" :: "r"(saddr), "l"(gptr))
#define CPA16(saddr, gptr) \
    asm volatile("cp.async.ca.shared.global [%0], [%1], 16;" :: "r"(saddr), "l"(gptr))
#define CP_COMMIT() asm volatile("cp.async.commit_group;" ::: "memory")
#define CP_WAIT2()  asm volatile("cp.async.wait_group 2;" ::: "memory")
#define CP_WAIT1()  asm volatile("cp.async.wait_group 1;" ::: "memory")
#define CP_WAIT0()  asm volatile("cp.async.wait_group 0;" ::: "memory")

__device__ __forceinline__ uint32_t pack_h2(float a, float b) {
    __half2 t(__float2half(a), __float2half(b));
    return *(uint32_t*)&t;
}

// ---------------------------------------------------------------------------
// prep_all: blocks [0, qblocks) do q prep (4 heads/warp, batched loads);
// remaining blocks convert weights fp32->fp16.
// ---------------------------------------------------------------------------
__global__ __launch_bounds__(256) void prep_all(
    const float* __restrict__ x, const float* __restrict__ cosb,
    const float* __restrict__ sinb,
    const float* __restrict__ kv_w, const float* __restrict__ proj_w,
    __half* __restrict__ a16, __half* __restrict__ q16,
    __half* __restrict__ b16, __half* __restrict__ c16,
    float qscale, int T, int total_heads, int qblocks, int wn4)
{
    if ((int)blockIdx.x >= qblocks) {
        int idx = (blockIdx.x - qblocks) * 256 + threadIdx.x;
        const float* src; __half* dst;
        if (idx < wn4) { src = kv_w; dst = b16; }
        else           { src = proj_w; dst = c16; idx -= wn4; }
        if (idx < wn4) {
            float4 v = ((const float4*)src)[idx];
            ((uint32_t*)dst)[2 * idx]     = pack_h2(v.x, v.y);
            ((uint32_t*)dst)[2 * idx + 1] = pack_h2(v.z, v.w);
        }
        return;
    }

    const int w0 = blockIdx.x * 32 + (threadIdx.x >> 5) * 4;
    if (w0 >= total_heads) return;
    const int lane = threadIdx.x & 31;

    // batched loads: 16 independent LDGs in flight
    float x1[4], x2[4], co[4], si[4];
#pragma unroll
    for (int j = 0; j < 4; j++) {
        const size_t ib = (size_t)(w0 + j) * DHEAD;
        x1[j] = x[ib + lane];
        x2[j] = x[ib + 32 + lane];
        const int t = ((w0 + j) / H_HEADS) % T;
        co[j] = cosb[t * 32 + lane];
        si[j] = sinb[t * 32 + lane];
    }

#pragma unroll
    for (int j = 0; j < 4; j++) {
        const int w = w0 + j;
        const size_t ib = (size_t)w * DHEAD;
        a16[ib + lane]      = __float2half(x1[j]);
        a16[ib + 32 + lane] = __float2half(x2[j]);

        float o1 = x1[j] * co[j] + x2[j] * si[j];
        float o2 = -x1[j] * si[j] + x2[j] * co[j];

        float ss = o1 * o1 + o2 * o2;
#pragma unroll
        for (int off = 16; off; off >>= 1)
            ss += __shfl_xor_sync(0xffffffffu, ss, off);
        float r = rsqrtf(ss * (1.0f / 64.0f) + RMS_EPS) * qscale;

        const int h = w % H_HEADS;
        const int t = (w / H_HEADS) % T;
        const int b = w / (H_HEADS * T);
        const size_t ob = ((size_t)(b * H_HEADS + h) * T + t) * DHEAD;
        q16[ob + lane]      = __float2half(o1 * r);
        q16[ob + 32 + lane] = __float2half(o2 * r);
    }
}

// ---------------------------------------------------------------------------
// 3-stage cp.async fp16 NT GEMM (R14 config — measured best 42.2us).
// ---------------------------------------------------------------------------
#define KCH2   32
#define ROWB2  80
#define MATB2  (128 * ROWB2)
#define STB2   (2 * MATB2)       // 20480 per stage
#define GEMM_SMEM (3 * STB2)     // 61440

template <bool FUSE_ROPE>
__global__ __launch_bounds__(256, 2) void gemm_mma(
    const __half* __restrict__ A, const __half* __restrict__ B,
    float* __restrict__ C,
    const float* __restrict__ cosb, const float* __restrict__ sinb,
    __half* __restrict__ O16,
    int M, int N, int K, int T)
{
    extern __shared__ char smem[];
    const uint32_t sb = smem_u32(smem);

    const int tid  = threadIdx.x;
    const int wid  = tid >> 5;
    const int lane = tid & 31;
    const int m0 = blockIdx.y * 128, n0 = blockIdx.x * 128;

    const int wm = (wid & 3) * 32;
    const int wn = (wid >> 2) * 64;

    const int a_row = (lane & 7) + (lane & 8);
    const int a_col = (lane >> 4) * 16;
    const int b_row = (lane & 7) + ((lane >> 4) & 1) * 8;
    const int b_col = ((lane >> 3) & 1) * 16;

    const int grow = tid >> 1;
    const uint32_t s_off = (uint32_t)grow * ROWB2 + (tid & 1) * 32;
    const int gelem = (tid & 1) * 16;

    const __half* gA = A + (size_t)(m0 + grow) * K + gelem;
    const __half* gB = B + (size_t)(n0 + grow) * K + gelem;

    float c[2][8][4];
#pragma unroll
    for (int i = 0; i < 2; i++)
#pragma unroll
        for (int j = 0; j < 8; j++)
#pragma unroll
            for (int e = 0; e < 4; e++) c[i][j][e] = 0.f;

    const int nchunk = K / KCH2;

    auto fill = [&](int stage, int ch) {
        const int k0 = ch * KCH2;
        uint32_t s0 = sb + stage * STB2 + s_off;
        const __half* a0 = gA + k0;
        const __half* b0 = gB + k0;
        CP16(s0,         a0);  CP16(s0 + 16,         a0 + 8);
        CP16(s0 + MATB2, b0);  CP16(s0 + MATB2 + 16, b0 + 8);
    };

    fill(0, 0); CP_COMMIT();
    if (nchunk > 1) { fill(1, 1); CP_COMMIT(); }

    int st = 0;
    for (int ch = 0; ch < nchunk; ch++) {
        if (ch + 2 < nchunk) fill((st + 2) % 3, ch + 2);
        CP_COMMIT();
        CP_WAIT2();
        __syncthreads();

        const uint32_t sA = sb + st * STB2;
        const uint32_t sB = sA + MATB2;

#pragma unroll
        for (int ks = 0; ks < 2; ks++) {
            const int kb = ks * 32;
            uint32_t ah[2][4], bh[4][4];
#pragma unroll
            for (int mi = 0; mi < 2; mi++) {
                uint32_t addr = sA + (uint32_t)(wm + mi * 16 + a_row) * ROWB2 + kb + a_col;
                LDSM_X4(ah[mi][0], ah[mi][1], ah[mi][2], ah[mi][3], addr);
            }
#pragma unroll
            for (int nb = 0; nb < 4; nb++) {
                uint32_t addr = sB + (uint32_t)(wn + nb * 16 + b_row) * ROWB2 + kb + b_col;
                LDSM_X4(bh[nb][0], bh[nb][1], bh[nb][2], bh[nb][3], addr);
            }
#pragma unroll
            for (int mi = 0; mi < 2; mi++)
#pragma unroll
                for (int nb = 0; nb < 4; nb++)
#pragma unroll
                    for (int sj = 0; sj < 2; sj++) {
                        float* cc = c[mi][nb * 2 + sj];
                        MMA_FP16(cc[0], cc[1], cc[2], cc[3],
                                 ah[mi][0], ah[mi][1], ah[mi][2], ah[mi][3],
                                 bh[nb][sj * 2], bh[nb][sj * 2 + 1]);
                    }
        }
        __syncthreads();
        st = (st + 1) % 3;
    }

    const int g  = lane >> 2;
    const int t2 = (lane & 3) * 2;

    if (!FUSE_ROPE) {
#pragma unroll
        for (int mi = 0; mi < 2; mi++) {
            float* r0 = C + (size_t)(m0 + wm + mi * 16 + g) * N + n0 + wn + t2;
            float* r1 = r0 + 8 * N;
#pragma unroll
            for (int nj = 0; nj < 8; nj++) {
                *(float2*)(r0 + nj * 8) = make_float2(c[mi][nj][0], c[mi][nj][1]);
                *(float2*)(r1 + nj * 8) = make_float2(c[mi][nj][2], c[mi][nj][3]);
            }
        }
    } else {
        const int h = (n0 + wn) >> 6;
#pragma unroll
        for (int mi = 0; mi < 2; mi++) {
#pragma unroll
            for (int half = 0; half < 2; half++) {
                const int m = m0 + wm + mi * 16 + g + half * 8;
                const int b = m / T, t = m % T;
                float o1[4][2], o2[4][2];
                float ss = 0.f;
#pragma unroll
                for (int nj = 0; nj < 4; nj++) {
#pragma unroll
                    for (int e = 0; e < 2; e++) {
                        const int d = nj * 8 + t2 + e;
                        float x1 = c[mi][nj][half * 2 + e];
                        float x2 = c[mi][nj + 4][half * 2 + e];
                        float co = cosb[t * 32 + d];
                        float si = sinb[t * 32 + d];
                        float a = x1 * co + x2 * si;
                        float bb = -x1 * si + x2 * co;
                        o1[nj][e] = a; o2[nj][e] = bb;
                        ss += a * a + bb * bb;
                    }
                }
                ss += __shfl_xor_sync(0xffffffffu, ss, 1);
                ss += __shfl_xor_sync(0xffffffffu, ss, 2);
                float r = rsqrtf(ss * (1.0f / 64.0f) + RMS_EPS);
                const size_t ob = ((size_t)(b * H_HEADS + h) * T + t) * DHEAD + t2;
#pragma unroll
                for (int nj = 0; nj < 4; nj++) {
                    *(uint32_t*)(O16 + ob + nj * 8)      = pack_h2(o1[nj][0] * r, o1[nj][1] * r);
                    *(uint32_t*)(O16 + ob + 32 + nj * 8) = pack_h2(o2[nj][0] * r, o2[nj][1] * r);
                }
            }
        }
    }
}

// ---------------------------------------------------------------------------
// Sliding-window attention, fp16, 128-row q-tile (R14 config) with
// offset-free exp2 (constant exp2 shift cancels in O/lsum).
// ---------------------------------------------------------------------------
#define ATT_ROWB 144
#define ATT_MAT  (64 * ATT_ROWB)

__global__ __launch_bounds__(256, 2) void attn_mma(
    const __half* __restrict__ Q16, const __half* __restrict__ KV16,
    __half* __restrict__ Out,
    const int* __restrict__ wl, int T)
{
    __shared__ char smc[2 * ATT_MAT];
    const uint32_t sbase = smem_u32(smc);

    const int tid = threadIdx.x, wid = tid >> 5, lane = tid & 31;
    const int mwarp = wid & 3, kgrp = wid >> 2;
    const int qt = blockIdx.x, h = blockIdx.y, b = blockIdx.z;
    const int q0 = qt * 128;
    const int W = *wl;
    const size_t hb = (size_t)(b * H_HEADS + h) * T * DHEAD;

    const int lrow = tid >> 2;
    const uint32_t s_off = (uint32_t)lrow * ATT_ROWB + (tid & 3) * 32;
    const int gcol = (tid & 3) * 16;

    const int a_row  = (lane & 7) + (lane & 8);
    const int a_colB = (lane >> 4) * 16;
    const int b_row  = (lane & 7) + ((lane >> 4) & 1) * 8;
    const int b_colB = ((lane >> 3) & 1) * 16;
    const int t_m = lane >> 3, t_r = lane & 7;

    auto fill_kv = [&](int st, int k0) {
        uint32_t s0 = sbase + st * ATT_MAT + s_off;
        const __half* gk = KV16 + hb + (size_t)(k0 + lrow) * DHEAD + gcol;
        CPA16(s0, gk);  CPA16(s0 + 16, gk + 8);
    };

    // stage Q: rows 0-63 in stage0, 64-127 in stage1; extract both m-frags
    {
        uint32_t s0 = sbase + s_off;
        const __half* gq = Q16 + hb + (size_t)(q0 + lrow) * DHEAD + gcol;
        CPA16(s0, gq);              CPA16(s0 + 16, gq + 8);
        const __half* gq1 = gq + (size_t)64 * DHEAD;
        CPA16(s0 + ATT_MAT, gq1);   CPA16(s0 + ATT_MAT + 16, gq1 + 8);
        CP_COMMIT();
        CP_WAIT0();
    }
    __syncthreads();
    uint32_t qf[2][4][4];
#pragma unroll
    for (int mi = 0; mi < 2; mi++)
#pragma unroll
        for (int kc = 0; kc < 4; kc++) {
            uint32_t ad = sbase + mi * ATT_MAT
                        + (uint32_t)(mwarp * 16 + a_row) * ATT_ROWB + kc * 32 + a_colB;
            LDSM_X4(qf[mi][kc][0], qf[mi][kc][1], qf[mi][kc][2], qf[mi][kc][3], ad);
        }
    __syncthreads();

    float o[2][8][4];
#pragma unroll
    for (int mi = 0; mi < 2; mi++)
#pragma unroll
        for (int i = 0; i < 8; i++)
#pragma unroll
            for (int e = 0; e < 4; e++) o[mi][i][e] = 0.f;
    float lsum[2][2] = {{0.f, 0.f}, {0.f, 0.f}};

    int lo_t = q0 - W; if (lo_t < 0) lo_t = 0;
    const int kt_lo = lo_t >> 6;
    const int kt_hi = (q0 + 127) >> 6;

    fill_kv(0, kt_lo * 64);
    CP_COMMIT();

    for (int kt = kt_lo; kt <= kt_hi; kt++) {
        const int k0 = kt * 64;
        const int st = (kt - kt_lo) & 1;
        if (kt < kt_hi) { fill_kv(st ^ 1, k0 + 64); CP_COMMIT(); CP_WAIT1(); }
        else            { CP_WAIT0(); }
        __syncthreads();

        const uint32_t sK = sbase + st * ATT_MAT;
        const bool fullt = (k0 + 63 <= q0) && (q0 + 127 - k0 <= W);

#pragma unroll
        for (int nc = 0; nc < 2; nc++) {
            const int n16 = kgrp * 2 + nc;

            float s[2][2][4];
#pragma unroll
            for (int mi = 0; mi < 2; mi++)
#pragma unroll
                for (int sj = 0; sj < 2; sj++)
#pragma unroll
                    for (int e = 0; e < 4; e++) s[mi][sj][e] = 0.f;

#pragma unroll
            for (int kc = 0; kc < 4; kc++) {
                uint32_t bf[4];
                uint32_t ad = sK + (uint32_t)(n16 * 16 + b_row) * ATT_ROWB + kc * 32 + b_colB;
                LDSM_X4(bf[0], bf[1], bf[2], bf[3], ad);
#pragma unroll
                for (int mi = 0; mi < 2; mi++) {
                    MMA_FP16(s[mi][0][0], s[mi][0][1], s[mi][0][2], s[mi][0][3],
                             qf[mi][kc][0], qf[mi][kc][1], qf[mi][kc][2], qf[mi][kc][3],
                             bf[0], bf[1]);
                    MMA_FP16(s[mi][1][0], s[mi][1][1], s[mi][1][2], s[mi][1][3],
                             qf[mi][kc][0], qf[mi][kc][1], qf[mi][kc][2], qf[mi][kc][3],
                             bf[2], bf[3]);
                }
            }

            if (!fullt) {
#pragma unroll
                for (int mi = 0; mi < 2; mi++) {
                    const int qr = q0 + mi * 64 + mwarp * 16 + (lane >> 2);
#pragma unroll
                    for (int sj = 0; sj < 2; sj++) {
                        const int kb = k0 + (n16 * 2 + sj) * 8 + (lane & 3) * 2;
#pragma unroll
                        for (int e = 0; e < 4; e++) {
                            int qq = qr + ((e >= 2) ? 8 : 0);
                            int kk = kb + (e & 1);
                            if (kk > qq || qq - kk > W) s[mi][sj][e] = -1e30f;
                        }
                    }
                }
            }

            uint32_t pf[2][4];
#pragma unroll
            for (int mi = 0; mi < 2; mi++) {
#pragma unroll
                for (int sj = 0; sj < 2; sj++)
#pragma unroll
                    for (int e = 0; e < 4; e++) {
                        float p = exp2f(s[mi][sj][e]);   // offset-free: cancels in O/lsum
                        s[mi][sj][e] = p;
                        lsum[mi][e >> 1] += p;
                    }
                pf[mi][0] = pack_h2(s[mi][0][0], s[mi][0][1]);
                pf[mi][1] = pack_h2(s[mi][0][2], s[mi][0][3]);
                pf[mi][2] = pack_h2(s[mi][1][0], s[mi][1][1]);
                pf[mi][3] = pack_h2(s[mi][1][2], s[mi][1][3]);
            }

#pragma unroll
            for (int dg = 0; dg < 4; dg++) {
                uint32_t vf[4];
                uint32_t ad = sK + (uint32_t)(n16 * 16 + t_r + (t_m & 1) * 8) * ATT_ROWB
                            + dg * 32 + (t_m >> 1) * 16;
                LDSM_X4_T(vf[0], vf[1], vf[2], vf[3], ad);
#pragma unroll
                for (int mi = 0; mi < 2; mi++) {
                    float* c0 = o[mi][dg * 2];
                    float* c1 = o[mi][dg * 2 + 1];
                    MMA_FP16(c0[0], c0[1], c0[2], c0[3],
                             pf[mi][0], pf[mi][1], pf[mi][2], pf[mi][3], vf[0], vf[1]);
                    MMA_FP16(c1[0], c1[1], c1[2], c1[3],
                             pf[mi][0], pf[mi][1], pf[mi][2], pf[mi][3], vf[2], vf[3]);
                }
            }
        }
        __syncthreads();
    }

    // epilogue: two-pass cross-group reduce (linear partials add)
    float* red = (float*)smc;
    const int g = lane >> 2, t2 = (lane & 3) * 2;
#pragma unroll
    for (int mi = 0; mi < 2; mi++) {
        __syncthreads();
        if (kgrp == 1) {
            float* dst = red + (tid - 128) * 34;
#pragma unroll
            for (int i = 0; i < 8; i++)
#pragma unroll
                for (int e = 0; e < 4; e++) dst[i * 4 + e] = o[mi][i][e];
            dst[32] = lsum[mi][0];
            dst[33] = lsum[mi][1];
        }
        __syncthreads();
        if (kgrp == 0) {
            const float* src = red + tid * 34;
            float oo[8][4];
#pragma unroll
            for (int i = 0; i < 8; i++)
#pragma unroll
                for (int e = 0; e < 4; e++) oo[i][e] = o[mi][i][e] + src[i * 4 + e];
            float s0 = lsum[mi][0] + src[32];
            float s1 = lsum[mi][1] + src[33];
            s0 += __shfl_xor_sync(0xffffffffu, s0, 1);
            s0 += __shfl_xor_sync(0xffffffffu, s0, 2);
            s1 += __shfl_xor_sync(0xffffffffu, s1, 1);
            s1 += __shfl_xor_sync(0xffffffffu, s1, 2);
            const float inv0 = 1.f / s0;
            const float inv1 = 1.f / s1;
            const size_t r0 = (size_t)(b * T + q0 + mi * 64 + mwarp * 16 + g) * 1024 + h * 64 + t2;
            const size_t r1 = r0 + (size_t)8 * 1024;
#pragma unroll
            for (int nj = 0; nj < 8; nj++) {
                *(uint32_t*)(Out + r0 + nj * 8) = pack_h2(oo[nj][0] * inv0, oo[nj][1] * inv0);
                *(uint32_t*)(Out + r1 + nj * 8) = pack_h2(oo[nj][2] * inv1, oo[nj][3] * inv1);
            }
        }
    }
}

// ---------------------------------------------------------------------------
extern "C" void kernel_launch(void* const* d_in, const int* in_sizes, int n_in,
                              void* d_out, int out_size)
{
    const float* x      = (const float*)d_in[0];
    const float* cosb   = (const float*)d_in[1];
    const float* sinb   = (const float*)d_in[2];
    const float* kv_w   = (const float*)d_in[3];
    const float* proj_w = (const float*)d_in[4];
    const int* wl       = (n_in >= 6) ? (const int*)d_in[5] : nullptr;

    const int T = in_sizes[1] / 32;
    const int C = 1024;
    const int B = in_sizes[0] / (T * C);
    const int M = B * T;
    const int total_heads = M * H_HEADS;

    __half *a16, *b16, *c16, *q16, *kv16;
    cudaGetSymbolAddress((void**)&a16,  g_a16);
    cudaGetSymbolAddress((void**)&b16,  g_b16);
    cudaGetSymbolAddress((void**)&c16,  g_c16);
    cudaGetSymbolAddress((void**)&q16,  g_q16);
    cudaGetSymbolAddress((void**)&kv16, g_kv16);

    cudaFuncSetAttribute(gemm_mma<true>,  cudaFuncAttributeMaxDynamicSharedMemorySize, GEMM_SMEM);
    cudaFuncSetAttribute(gemm_mma<false>, cudaFuncAttributeMaxDynamicSharedMemorySize, GEMM_SMEM);

    // 1) fused prep: q rope/rms (4 heads/warp) + x fp16 + weight conversions
    {
        const int qblocks = (total_heads + 31) / 32;
        const int wn4 = C * C / 4;
        const int wblocks = (2 * wn4 + 255) / 256;
        prep_all<<<qblocks + wblocks, 256>>>(x, cosb, sinb, kv_w, proj_w,
                                             a16, q16, b16, c16,
                                             0.125f * LOG2E, T, total_heads,
                                             qblocks, wn4);
    }
    // 2) kv = rope(rms(x @ kv_w^T)), fused epilogue
    {
        dim3 grid(C / 128, M / 128);
        gemm_mma<true><<<grid, 256, GEMM_SMEM>>>(a16, b16, nullptr,
                                                 cosb, sinb, kv16, M, C, C, T);
    }
    // 3) attention
    {
        dim3 grid(T / 128, H_HEADS, B);
        attn_mma<<<grid, 256>>>(q16, kv16, a16, wl, T);
    }
    // 4) out = attn @ proj_w^T
    {
        dim3 grid(C / 128, M / 128);
        gemm_mma<false><<<grid, 256, GEMM_SMEM>>>(a16, c16, (float*)d_out,
                                                  nullptr, nullptr, nullptr, M, C, C, T);
    }
}